// round 9
// baseline (speedup 1.0000x reference)
#include <cuda_runtime.h>
#include <math.h>

#define BX 32
#define BY 8
#define TPT_X 4               // outputs per thread, x
#define TPT_Y 4               // outputs per thread, y
#define TILE_W (BX * TPT_X)   // 128
#define TILE_H (BY * TPT_Y)   // 32
#define SM_W (TILE_W + 4)     // 132
#define SM_H (TILE_H + 4)     // 36

// (256, 5): cap regs at 51 -> 5 resident blocks/SM (62.5% occ) instead of 4.
__global__ __launch_bounds__(BX * BY, 5)
void hitmiss_kernel(const float* __restrict__ in,
                    const float* __restrict__ Kh,
                    const float* __restrict__ Km,
                    float* __restrict__ out,
                    int H, int W, int Hout, int Wout)
{
    __shared__ __align__(16) float tile[SM_H][SM_W];

    const int tid  = threadIdx.y * BX + threadIdx.x;
    const int col0 = blockIdx.x * TILE_W;
    const int row0 = blockIdx.y * TILE_H;

    // 96.8% of blocks: fully interior -> no divisions, no clamps, no predicates.
    const bool interior = (row0 + SM_H <= H) && (col0 + SM_W <= W);

    if (interior) {
        // --- fast loader first: get DRAM loads in flight early ---
        const float* base = in + (size_t)row0 * W + col0;
        const int tx4 = threadIdx.x * 4;
#pragma unroll
        for (int i = 0; i < 4; ++i) {                 // rows 0..31
            const int r = threadIdx.y + 8 * i;
            *reinterpret_cast<float4*>(&tile[r][tx4]) =
                *reinterpret_cast<const float4*>(base + (size_t)r * W + tx4);
        }
        if (threadIdx.y < 4) {                        // rows 32..35
            const int r = 32 + threadIdx.y;
            *reinterpret_cast<float4*>(&tile[r][tx4]) =
                *reinterpret_cast<const float4*>(base + (size_t)r * W + tx4);
        }
        if (tid < SM_H) {                             // last float4 column (128..131)
            *reinterpret_cast<float4*>(&tile[tid][TILE_W]) =
                *reinterpret_cast<const float4*>(base + (size_t)tid * W + TILE_W);
        }
    } else {
        // --- boundary loader (rare): generic with clamps ---
        const int NW4 = SM_W / 4;          // 33
        const int NV  = NW4 * SM_H;        // 1188 float4 slots
        for (int idx = tid; idx < NV; idx += BX * BY) {
            int r  = idx / NW4;
            int c4 = idx - r * NW4;
            int gr = row0 + r; if (gr > H - 1) gr = H - 1;
            int gc = col0 + c4 * 4;
            float4 v;
            if (gc + 3 <= W - 1) {
                v = *reinterpret_cast<const float4*>(in + (size_t)gr * W + gc);
            } else {
                int c0 = gc     < W - 1 ? gc     : W - 1;
                int c1 = gc + 1 < W - 1 ? gc + 1 : W - 1;
                int c2 = gc + 2 < W - 1 ? gc + 2 : W - 1;
                int c3 = gc + 3 < W - 1 ? gc + 3 : W - 1;
                const float* rowp = in + (size_t)gr * W;
                v.x = rowp[c0]; v.y = rowp[c1]; v.z = rowp[c2]; v.w = rowp[c3];
            }
            *reinterpret_cast<float4*>(&tile[r][c4 * 4]) = v;
        }
    }

    // --- kernels into registers (warp-uniform broadcast loads, L1-hit) ---
    float kh[25], km[25];
#pragma unroll
    for (int i = 0; i < 25; ++i) {
        kh[i] = __ldg(Kh + i);
        km[i] = __ldg(Km + i);
    }

    __syncthreads();

    // --- 4x4 register-blocked hit-or-miss, row-streaming, FMNMX3 trees ---
    const int lx = threadIdx.x * TPT_X;   // multiple of 4 -> aligned LDS.128
    const int ly = threadIdx.y * TPT_Y;

    float mn[TPT_Y * TPT_X], mx[TPT_Y * TPT_X];

#pragma unroll
    for (int r = 0; r < TPT_Y + 4; ++r) {          // 8 input rows
        float w[TPT_X + 4];
        float4 a = *reinterpret_cast<const float4*>(&tile[ly + r][lx]);
        float4 b = *reinterpret_cast<const float4*>(&tile[ly + r][lx + 4]);
        w[0] = a.x; w[1] = a.y; w[2] = a.z; w[3] = a.w;
        w[4] = b.x; w[5] = b.y; w[6] = b.z; w[7] = b.w;

#pragma unroll
        for (int orow = 0; orow < TPT_Y; ++orow) {
            const int di = r - orow;
            if (di < 0 || di > 4) continue;          // compile-time pruned
#pragma unroll
            for (int oc = 0; oc < TPT_X; ++oc) {
                const int o = orow * TPT_X + oc;

                float h0 = w[oc + 0] - kh[di * 5 + 0];
                float h1 = w[oc + 1] - kh[di * 5 + 1];
                float h2 = w[oc + 2] - kh[di * 5 + 2];
                float h3 = w[oc + 3] - kh[di * 5 + 3];
                float h4 = w[oc + 4] - kh[di * 5 + 4];
                float m0 = w[oc + 0] - km[di * 5 + 0];
                float m1 = w[oc + 1] - km[di * 5 + 1];
                float m2 = w[oc + 2] - km[di * 5 + 2];
                float m3 = w[oc + 3] - km[di * 5 + 3];
                float m4 = w[oc + 4] - km[di * 5 + 4];

                if (di == 0) {
                    // optimal 5->1 with 3-input ops: exactly 2 FMNMX3
                    mn[o] = fminf(fminf(fminf(h0, h1), h2), fminf(h3, h4) == fminf(h3, h4) ? fminf(h3, h4) : fminf(h3, h4));
                    mn[o] = fminf(fminf(fminf(fminf(h0, h1), h2), h3), h4);
                    mx[o] = fmaxf(fmaxf(fmaxf(fmaxf(m0, m1), m2), m3), m4);
                } else {
                    // 6 inputs -> 1: optimal 3 ops (2x FMNMX3 + merge)
                    float tA = fminf(fminf(h0, h1), h2);       // FMNMX3
                    float tB = fminf(fminf(h3, h4), mn[o]);    // FMNMX3
                    mn[o] = fminf(tA, tB);
                    float uA = fmaxf(fmaxf(m0, m1), m2);       // FMNMX3
                    float uB = fmaxf(fmaxf(m3, m4), mx[o]);    // FMNMX3
                    mx[o] = fmaxf(uA, uB);
                }
            }
        }
    }

    // --- stores ---
    const int oc0 = col0 + lx;
    const int or0 = row0 + ly;
    if (interior && (oc0 + 3 < Wout) && (or0 + TPT_Y <= Hout)) {
        float* p = out + (size_t)or0 * Wout + oc0;
#pragma unroll
        for (int orow = 0; orow < TPT_Y; ++orow) {
            float4 o;
            o.x = mn[orow * TPT_X + 0] - mx[orow * TPT_X + 0];
            o.y = mn[orow * TPT_X + 1] - mx[orow * TPT_X + 1];
            o.z = mn[orow * TPT_X + 2] - mx[orow * TPT_X + 2];
            o.w = mn[orow * TPT_X + 3] - mx[orow * TPT_X + 3];
            *reinterpret_cast<float4*>(p) = o;
            p += Wout;
        }
    } else {
#pragma unroll
        for (int orow = 0; orow < TPT_Y; ++orow) {
            const int gro = or0 + orow;
            if (gro >= Hout) continue;
            float r0 = mn[orow * TPT_X + 0] - mx[orow * TPT_X + 0];
            float r1 = mn[orow * TPT_X + 1] - mx[orow * TPT_X + 1];
            float r2 = mn[orow * TPT_X + 2] - mx[orow * TPT_X + 2];
            float r3 = mn[orow * TPT_X + 3] - mx[orow * TPT_X + 3];
            float* orow_p = out + (size_t)gro * Wout;
            if (oc0 + 0 < Wout) orow_p[oc0 + 0] = r0;
            if (oc0 + 1 < Wout) orow_p[oc0 + 1] = r1;
            if (oc0 + 2 < Wout) orow_p[oc0 + 2] = r2;
            if (oc0 + 3 < Wout) orow_p[oc0 + 3] = r3;
        }
    }
}

extern "C" void kernel_launch(void* const* d_in, const int* in_sizes, int n_in,
                              void* d_out, int out_size)
{
    const float* in = (const float*)d_in[0];
    const float* Kh = (const float*)d_in[1];
    const float* Km = (const float*)d_in[2];
    float* out = (float*)d_out;

    const int H = (int)lround(sqrt((double)in_sizes[0]));
    const int W = H;
    const int Hout = H - 4;
    const int Wout = W - 4;

    dim3 block(BX, BY);
    dim3 grid((Wout + TILE_W - 1) / TILE_W, (Hout + TILE_H - 1) / TILE_H);
    hitmiss_kernel<<<grid, block>>>(in, Kh, Km, out, H, W, Hout, Wout);
}

// round 10
// speedup vs baseline: 1.0111x; 1.0111x over previous
#include <cuda_runtime.h>
#include <cuda_pipeline.h>
#include <math.h>

#define BX 32
#define BY 8
#define TPT_X 4               // outputs per thread, x
#define TPT_Y 4               // outputs per thread, y
#define TILE_W (BX * TPT_X)   // 128
#define TILE_H (BY * TPT_Y)   // 32
#define SM_W (TILE_W + 4)     // 132
#define SM_H (TILE_H + 4)     // 36

// ---------- interior tile fill via cp.async (no registers, overlappable) ----------
__device__ __forceinline__ void fill_async(float (*t)[SM_W],
                                           const float* __restrict__ in,
                                           int row0, int col0, int W,
                                           int tid)
{
    const float* base = in + (size_t)row0 * W + col0;
    const int tx4 = threadIdx.x * 4;
#pragma unroll
    for (int i = 0; i < 4; ++i) {                 // rows 0..31
        const int r = threadIdx.y + 8 * i;
        __pipeline_memcpy_async(&t[r][tx4], base + (size_t)r * W + tx4, 16);
    }
    if (threadIdx.y < 4) {                        // rows 32..35
        const int r = 32 + threadIdx.y;
        __pipeline_memcpy_async(&t[r][tx4], base + (size_t)r * W + tx4, 16);
    }
    if (tid < SM_H) {                             // last float4 column (128..131)
        __pipeline_memcpy_async(&t[tid][TILE_W], base + (size_t)tid * W + TILE_W, 16);
    }
}

// ---------- boundary tile fill (rare): synchronous generic with clamps ----------
__device__ void fill_generic(float (*t)[SM_W],
                             const float* __restrict__ in,
                             int row0, int col0, int H, int W, int tid)
{
    const int NW4 = SM_W / 4;          // 33
    const int NV  = NW4 * SM_H;        // 1188 float4 slots
    for (int idx = tid; idx < NV; idx += BX * BY) {
        int r  = idx / NW4;
        int c4 = idx - r * NW4;
        int gr = row0 + r; if (gr > H - 1) gr = H - 1;
        int gc = col0 + c4 * 4;
        float4 v;
        if (gc + 3 <= W - 1) {
            v = *reinterpret_cast<const float4*>(in + (size_t)gr * W + gc);
        } else {
            int c0 = gc     < W - 1 ? gc     : W - 1;
            int c1 = gc + 1 < W - 1 ? gc + 1 : W - 1;
            int c2 = gc + 2 < W - 1 ? gc + 2 : W - 1;
            int c3 = gc + 3 < W - 1 ? gc + 3 : W - 1;
            const float* rowp = in + (size_t)gr * W;
            v.x = rowp[c0]; v.y = rowp[c1]; v.z = rowp[c2]; v.w = rowp[c3];
        }
        *reinterpret_cast<float4*>(&t[r][c4 * 4]) = v;
    }
}

// ---------- hit-or-miss over one 128x32 tile (R8 math body, FMNMX3 trees) ----------
__device__ __forceinline__ void compute_tile(const float (*tile)[SM_W],
                                             const float* kh, const float* km,
                                             float* __restrict__ out,
                                             int col0, int orow0,
                                             int Hout, int Wout,
                                             int lx, int ly)
{
    float mn[TPT_Y * TPT_X], mx[TPT_Y * TPT_X];

#pragma unroll
    for (int r = 0; r < TPT_Y + 4; ++r) {          // 8 input rows
        float w[TPT_X + 4];
        float4 a = *reinterpret_cast<const float4*>(&tile[ly + r][lx]);
        float4 b = *reinterpret_cast<const float4*>(&tile[ly + r][lx + 4]);
        w[0] = a.x; w[1] = a.y; w[2] = a.z; w[3] = a.w;
        w[4] = b.x; w[5] = b.y; w[6] = b.z; w[7] = b.w;

#pragma unroll
        for (int orow = 0; orow < TPT_Y; ++orow) {
            const int di = r - orow;
            if (di < 0 || di > 4) continue;          // compile-time pruned
#pragma unroll
            for (int oc = 0; oc < TPT_X; ++oc) {
                const int o = orow * TPT_X + oc;

                float h0 = w[oc + 0] - kh[di * 5 + 0];
                float h1 = w[oc + 1] - kh[di * 5 + 1];
                float h2 = w[oc + 2] - kh[di * 5 + 2];
                float h3 = w[oc + 3] - kh[di * 5 + 3];
                float h4 = w[oc + 4] - kh[di * 5 + 4];
                float m0 = w[oc + 0] - km[di * 5 + 0];
                float m1 = w[oc + 1] - km[di * 5 + 1];
                float m2 = w[oc + 2] - km[di * 5 + 2];
                float m3 = w[oc + 3] - km[di * 5 + 3];
                float m4 = w[oc + 4] - km[di * 5 + 4];

                if (di == 0) {
                    // 5 -> 1 in exactly 2 fused ops (FMNMX3 + FMNMX3)
                    mn[o] = fminf(fminf(fminf(fminf(h0, h1), h2), h3), h4);
                    mx[o] = fmaxf(fmaxf(fmaxf(fmaxf(m0, m1), m2), m3), m4);
                } else {
                    // 6 -> 1: two FMNMX3 + merge
                    float tA = fminf(fminf(h0, h1), h2);
                    float tB = fminf(fminf(h3, h4), mn[o]);
                    mn[o] = fminf(tA, tB);
                    float uA = fmaxf(fmaxf(m0, m1), m2);
                    float uB = fmaxf(fmaxf(m3, m4), mx[o]);
                    mx[o] = fmaxf(uA, uB);
                }
            }
        }
    }

    const int oc0 = col0 + lx;
    const int or0 = orow0 + ly;
    if ((oc0 + 3 < Wout) && (or0 + TPT_Y <= Hout)) {
        float* p = out + (size_t)or0 * Wout + oc0;
#pragma unroll
        for (int orow = 0; orow < TPT_Y; ++orow) {
            float4 o;
            o.x = mn[orow * TPT_X + 0] - mx[orow * TPT_X + 0];
            o.y = mn[orow * TPT_X + 1] - mx[orow * TPT_X + 1];
            o.z = mn[orow * TPT_X + 2] - mx[orow * TPT_X + 2];
            o.w = mn[orow * TPT_X + 3] - mx[orow * TPT_X + 3];
            *reinterpret_cast<float4*>(p) = o;
            p += Wout;
        }
    } else {
#pragma unroll
        for (int orow = 0; orow < TPT_Y; ++orow) {
            const int gro = or0 + orow;
            if (gro >= Hout) continue;
            float r0 = mn[orow * TPT_X + 0] - mx[orow * TPT_X + 0];
            float r1 = mn[orow * TPT_X + 1] - mx[orow * TPT_X + 1];
            float r2 = mn[orow * TPT_X + 2] - mx[orow * TPT_X + 2];
            float r3 = mn[orow * TPT_X + 3] - mx[orow * TPT_X + 3];
            float* orow_p = out + (size_t)gro * Wout;
            if (oc0 + 0 < Wout) orow_p[oc0 + 0] = r0;
            if (oc0 + 1 < Wout) orow_p[oc0 + 1] = r1;
            if (oc0 + 2 < Wout) orow_p[oc0 + 2] = r2;
            if (oc0 + 3 < Wout) orow_p[oc0 + 3] = r3;
        }
    }
}

__global__ __launch_bounds__(BX * BY)
void hitmiss_kernel(const float* __restrict__ in,
                    const float* __restrict__ Kh,
                    const float* __restrict__ Km,
                    float* __restrict__ out,
                    int H, int W, int Hout, int Wout)
{
    __shared__ __align__(16) float tile[2][SM_H][SM_W];   // 38 KB double buffer

    const int tid  = threadIdx.y * BX + threadIdx.x;
    const int col0 = blockIdx.x * TILE_W;
    const int row0 = blockIdx.y * (2 * TILE_H);           // two vertical tiles per block
    const int row1 = row0 + TILE_H;

    const bool colInt = (col0 + SM_W <= W);
    const bool int0 = colInt && (row0 + SM_H <= H);
    const bool int1 = colInt && (row1 + SM_H <= H);

    // taps into registers (warp-uniform broadcast loads)
    float kh[25], km[25];
#pragma unroll
    for (int i = 0; i < 25; ++i) {
        kh[i] = __ldg(Kh + i);
        km[i] = __ldg(Km + i);
    }

    // --- pipelined fills: buf1's DRAM traffic overlaps tile0 compute ---
    if (int0) fill_async(tile[0], in, row0, col0, W, tid);
    else      fill_generic(tile[0], in, row0, col0, H, W, tid);
    __pipeline_commit();

    if (int1) fill_async(tile[1], in, row1, col0, W, tid);
    else      fill_generic(tile[1], in, row1, col0, H, W, tid);
    __pipeline_commit();

    __pipeline_wait_prior(1);          // buf0 complete
    __syncthreads();

    const int lx = threadIdx.x * TPT_X;
    const int ly = threadIdx.y * TPT_Y;

    compute_tile(tile[0], kh, km, out, col0, row0, Hout, Wout, lx, ly);

    __pipeline_wait_prior(0);          // buf1 complete
    __syncthreads();

    if (row1 < Hout)
        compute_tile(tile[1], kh, km, out, col0, row1, Hout, Wout, lx, ly);
}

extern "C" void kernel_launch(void* const* d_in, const int* in_sizes, int n_in,
                              void* d_out, int out_size)
{
    const float* in = (const float*)d_in[0];
    const float* Kh = (const float*)d_in[1];
    const float* Km = (const float*)d_in[2];
    float* out = (float*)d_out;

    const int H = (int)lround(sqrt((double)in_sizes[0]));
    const int W = H;
    const int Hout = H - 4;
    const int Wout = W - 4;

    dim3 block(BX, BY);
    dim3 grid((Wout + TILE_W - 1) / TILE_W,
              (Hout + 2 * TILE_H - 1) / (2 * TILE_H));
    hitmiss_kernel<<<grid, block>>>(in, Kh, Km, out, H, W, Hout, Wout);
}

// round 11
// speedup vs baseline: 1.0413x; 1.0298x over previous
#include <cuda_runtime.h>
#include <math.h>

#define BX 32
#define BY 8
#define TPT_X 4               // outputs per thread, x
#define TPT_Y 4               // outputs per thread, y
#define TILE_W (BX * TPT_X)   // 128
#define TILE_H (BY * TPT_Y)   // 32
#define SM_W (TILE_W + 4)     // 132
#define SM_H (TILE_H + 4)     // 36

__global__ __launch_bounds__(BX * BY)
void hitmiss_kernel(const float* __restrict__ in,
                    const float* __restrict__ Kh,
                    const float* __restrict__ Km,
                    float* __restrict__ out,
                    int H, int W, int Hout, int Wout)
{
    __shared__ __align__(16) float tile[SM_H][SM_W];

    const int tid  = threadIdx.y * BX + threadIdx.x;
    const int col0 = blockIdx.x * TILE_W;
    const int row0 = blockIdx.y * TILE_H;

    // 96.8% of blocks: fully interior -> no divisions, no clamps, no predicates.
    const bool interior = (row0 + SM_H <= H) && (col0 + SM_W <= W);

    // --- taps via vectorized broadcast loads: 13 LDG instead of 50 ---
    float kh[25], km[25];
    {
        const float4* Kh4 = reinterpret_cast<const float4*>(Kh);
        const float4* Km4 = reinterpret_cast<const float4*>(Km);
#pragma unroll
        for (int i = 0; i < 6; ++i) {
            float4 a = __ldg(Kh4 + i);
            kh[4*i+0] = a.x; kh[4*i+1] = a.y; kh[4*i+2] = a.z; kh[4*i+3] = a.w;
            float4 b = __ldg(Km4 + i);
            km[4*i+0] = b.x; km[4*i+1] = b.y; km[4*i+2] = b.z; km[4*i+3] = b.w;
        }
        kh[24] = __ldg(Kh + 24);
        km[24] = __ldg(Km + 24);
    }

    if (interior) {
        // --- fast loader: straight-line 2D indexing, all LDG.128 aligned ---
        const float* base = in + (size_t)row0 * W + col0;
        const int tx4 = threadIdx.x * 4;
#pragma unroll
        for (int i = 0; i < 4; ++i) {                 // rows 0..31
            const int r = threadIdx.y + 8 * i;
            *reinterpret_cast<float4*>(&tile[r][tx4]) =
                *reinterpret_cast<const float4*>(base + (size_t)r * W + tx4);
        }
        if (threadIdx.y < 4) {                        // rows 32..35
            const int r = 32 + threadIdx.y;
            *reinterpret_cast<float4*>(&tile[r][tx4]) =
                *reinterpret_cast<const float4*>(base + (size_t)r * W + tx4);
        }
        if (tid < SM_H) {                             // last float4 column (128..131)
            *reinterpret_cast<float4*>(&tile[tid][TILE_W]) =
                *reinterpret_cast<const float4*>(base + (size_t)tid * W + TILE_W);
        }
    } else {
        // --- boundary loader (rare): generic with clamps ---
        const int NW4 = SM_W / 4;          // 33
        const int NV  = NW4 * SM_H;        // 1188 float4 slots
        for (int idx = tid; idx < NV; idx += BX * BY) {
            int r  = idx / NW4;
            int c4 = idx - r * NW4;
            int gr = row0 + r; if (gr > H - 1) gr = H - 1;
            int gc = col0 + c4 * 4;
            float4 v;
            if (gc + 3 <= W - 1) {
                v = *reinterpret_cast<const float4*>(in + (size_t)gr * W + gc);
            } else {
                int c0 = gc     < W - 1 ? gc     : W - 1;
                int c1 = gc + 1 < W - 1 ? gc + 1 : W - 1;
                int c2 = gc + 2 < W - 1 ? gc + 2 : W - 1;
                int c3 = gc + 3 < W - 1 ? gc + 3 : W - 1;
                const float* rowp = in + (size_t)gr * W;
                v.x = rowp[c0]; v.y = rowp[c1]; v.z = rowp[c2]; v.w = rowp[c3];
            }
            *reinterpret_cast<float4*>(&tile[r][c4 * 4]) = v;
        }
    }
    __syncthreads();

    // --- 4x4 register-blocked hit-or-miss, row-streaming, FMNMX3 trees ---
    const int lx = threadIdx.x * TPT_X;   // multiple of 4 -> aligned LDS.128
    const int ly = threadIdx.y * TPT_Y;

    float mn[TPT_Y * TPT_X], mx[TPT_Y * TPT_X];

#pragma unroll
    for (int r = 0; r < TPT_Y + 4; ++r) {          // 8 input rows
        float w[TPT_X + 4];
        float4 a = *reinterpret_cast<const float4*>(&tile[ly + r][lx]);
        float4 b = *reinterpret_cast<const float4*>(&tile[ly + r][lx + 4]);
        w[0] = a.x; w[1] = a.y; w[2] = a.z; w[3] = a.w;
        w[4] = b.x; w[5] = b.y; w[6] = b.z; w[7] = b.w;

#pragma unroll
        for (int orow = 0; orow < TPT_Y; ++orow) {
            const int di = r - orow;
            if (di < 0 || di > 4) continue;          // compile-time pruned
#pragma unroll
            for (int oc = 0; oc < TPT_X; ++oc) {
                const int o = orow * TPT_X + oc;

                float h0 = w[oc + 0] - kh[di * 5 + 0];
                float h1 = w[oc + 1] - kh[di * 5 + 1];
                float h2 = w[oc + 2] - kh[di * 5 + 2];
                float h3 = w[oc + 3] - kh[di * 5 + 3];
                float h4 = w[oc + 4] - kh[di * 5 + 4];
                float m0 = w[oc + 0] - km[di * 5 + 0];
                float m1 = w[oc + 1] - km[di * 5 + 1];
                float m2 = w[oc + 2] - km[di * 5 + 2];
                float m3 = w[oc + 3] - km[di * 5 + 3];
                float m4 = w[oc + 4] - km[di * 5 + 4];

                if (di == 0) {
                    // 5 -> 1 in exactly 2 fused ops (FMNMX3 + FMNMX3)
                    mn[o] = fminf(fminf(fminf(fminf(h0, h1), h2), h3), h4);
                    mx[o] = fmaxf(fmaxf(fmaxf(fmaxf(m0, m1), m2), m3), m4);
                } else {
                    // 6 -> 1: two FMNMX3 + merge
                    float tA = fminf(fminf(h0, h1), h2);       // FMNMX3
                    float tB = fminf(fminf(h3, h4), mn[o]);    // FMNMX3
                    mn[o] = fminf(tA, tB);
                    float uA = fmaxf(fmaxf(m0, m1), m2);       // FMNMX3
                    float uB = fmaxf(fmaxf(m3, m4), mx[o]);    // FMNMX3
                    mx[o] = fmaxf(uA, uB);
                }
            }
        }
    }

    // --- stores ---
    const int oc0 = col0 + lx;
    const int or0 = row0 + ly;
    if (interior && (oc0 + 3 < Wout) && (or0 + TPT_Y <= Hout)) {
        float* p = out + (size_t)or0 * Wout + oc0;
#pragma unroll
        for (int orow = 0; orow < TPT_Y; ++orow) {
            float4 o;
            o.x = mn[orow * TPT_X + 0] - mx[orow * TPT_X + 0];
            o.y = mn[orow * TPT_X + 1] - mx[orow * TPT_X + 1];
            o.z = mn[orow * TPT_X + 2] - mx[orow * TPT_X + 2];
            o.w = mn[orow * TPT_X + 3] - mx[orow * TPT_X + 3];
            *reinterpret_cast<float4*>(p) = o;
            p += Wout;
        }
    } else {
#pragma unroll
        for (int orow = 0; orow < TPT_Y; ++orow) {
            const int gro = or0 + orow;
            if (gro >= Hout) continue;
            float r0 = mn[orow * TPT_X + 0] - mx[orow * TPT_X + 0];
            float r1 = mn[orow * TPT_X + 1] - mx[orow * TPT_X + 1];
            float r2 = mn[orow * TPT_X + 2] - mx[orow * TPT_X + 2];
            float r3 = mn[orow * TPT_X + 3] - mx[orow * TPT_X + 3];
            float* orow_p = out + (size_t)gro * Wout;
            if (oc0 + 0 < Wout) orow_p[oc0 + 0] = r0;
            if (oc0 + 1 < Wout) orow_p[oc0 + 1] = r1;
            if (oc0 + 2 < Wout) orow_p[oc0 + 2] = r2;
            if (oc0 + 3 < Wout) orow_p[oc0 + 3] = r3;
        }
    }
}

extern "C" void kernel_launch(void* const* d_in, const int* in_sizes, int n_in,
                              void* d_out, int out_size)
{
    const float* in = (const float*)d_in[0];
    const float* Kh = (const float*)d_in[1];
    const float* Km = (const float*)d_in[2];
    float* out = (float*)d_out;

    const int H = (int)lround(sqrt((double)in_sizes[0]));
    const int W = H;
    const int Hout = H - 4;
    const int Wout = W - 4;

    dim3 block(BX, BY);
    dim3 grid((Wout + TILE_W - 1) / TILE_W, (Hout + TILE_H - 1) / TILE_H);
    hitmiss_kernel<<<grid, block>>>(in, Kh, Km, out, H, W, Hout, Wout);
}